// round 2
// baseline (speedup 1.0000x reference)
#include <cuda_runtime.h>
#include <cstdint>

// Problem constants (fixed shapes for this problem instance)
#define D         256          // DIN == DOUT == 256
#define KNB       16           // neighbors per source
#define S_MAX     50000

// Scratch for aggregation outputs (pre-scatter). 50000*256 floats = 51.2 MB.
__device__ float4 g_scratch[(size_t)S_MAX * (D / 4)];

// ---------------------------------------------------------------------------
// Kernel 1: supports[M, 256] = A[M, 256] @ W[256, 256]^T + b
// 128x128 block tile, k-chunk 16, 8x8 per thread, 256 threads.
// ---------------------------------------------------------------------------
__global__ __launch_bounds__(256) void gemm_bias_kernel(
    const float* __restrict__ A,   // [M, 256]
    const float* __restrict__ W,   // [256, 256]
    const float* __restrict__ bias,// [256]
    float* __restrict__ C,         // [M, 256]
    int M)
{
    __shared__ float As[16][132];
    __shared__ float Bs[16][132];

    const int t  = threadIdx.x;
    const int tx = t & 15;          // N direction (8 cols each)
    const int ty = t >> 4;          // M direction (8 rows each)
    const int row0 = blockIdx.x * 128;
    const int col0 = blockIdx.y * 128;

    float acc[8][8];
#pragma unroll
    for (int i = 0; i < 8; i++)
#pragma unroll
        for (int j = 0; j < 8; j++) acc[i][j] = 0.f;

    for (int kk = 0; kk < D; kk += 16) {
        // Load A tile: 128 rows x 16 k = 512 float4, 2 per thread
#pragma unroll
        for (int it = 0; it < 2; it++) {
            int f  = t + it * 256;
            int r  = f >> 2;             // 0..127
            int kq = (f & 3) << 2;       // 0,4,8,12
            int gr = row0 + r;
            float4 v = make_float4(0.f, 0.f, 0.f, 0.f);
            if (gr < M)
                v = *reinterpret_cast<const float4*>(&A[(size_t)gr * D + kk + kq]);
            As[kq + 0][r] = v.x; As[kq + 1][r] = v.y;
            As[kq + 2][r] = v.z; As[kq + 3][r] = v.w;
        }
        // Load W tile (cols of C = rows of W): always in range (DOUT=256)
#pragma unroll
        for (int it = 0; it < 2; it++) {
            int f  = t + it * 256;
            int r  = f >> 2;
            int kq = (f & 3) << 2;
            float4 v = *reinterpret_cast<const float4*>(&W[(size_t)(col0 + r) * D + kk + kq]);
            Bs[kq + 0][r] = v.x; Bs[kq + 1][r] = v.y;
            Bs[kq + 2][r] = v.z; Bs[kq + 3][r] = v.w;
        }
        __syncthreads();

#pragma unroll
        for (int k = 0; k < 16; k++) {
            float4 a0 = *reinterpret_cast<const float4*>(&As[k][ty * 8 + 0]);
            float4 a1 = *reinterpret_cast<const float4*>(&As[k][ty * 8 + 4]);
            float4 b0 = *reinterpret_cast<const float4*>(&Bs[k][tx * 8 + 0]);
            float4 b1 = *reinterpret_cast<const float4*>(&Bs[k][tx * 8 + 4]);
            float av[8] = {a0.x, a0.y, a0.z, a0.w, a1.x, a1.y, a1.z, a1.w};
            float bv[8] = {b0.x, b0.y, b0.z, b0.w, b1.x, b1.y, b1.z, b1.w};
#pragma unroll
            for (int i = 0; i < 8; i++)
#pragma unroll
                for (int j = 0; j < 8; j++)
                    acc[i][j] = fmaf(av[i], bv[j], acc[i][j]);
        }
        __syncthreads();
    }

    // Bias + store (vectorized)
    float4 bb0 = *reinterpret_cast<const float4*>(&bias[col0 + tx * 8 + 0]);
    float4 bb1 = *reinterpret_cast<const float4*>(&bias[col0 + tx * 8 + 4]);
#pragma unroll
    for (int i = 0; i < 8; i++) {
        int gr = row0 + ty * 8 + i;
        if (gr >= M) continue;
        float4 o0 = make_float4(acc[i][0] + bb0.x, acc[i][1] + bb0.y,
                                acc[i][2] + bb0.z, acc[i][3] + bb0.w);
        float4 o1 = make_float4(acc[i][4] + bb1.x, acc[i][5] + bb1.y,
                                acc[i][6] + bb1.z, acc[i][7] + bb1.w);
        *reinterpret_cast<float4*>(&C[(size_t)gr * D + col0 + tx * 8 + 0]) = o0;
        *reinterpret_cast<float4*>(&C[(size_t)gr * D + col0 + tx * 8 + 4]) = o1;
    }
}

// ---------------------------------------------------------------------------
// Kernel 2: masked neighbor aggregation + residual + LeakyReLU -> scratch.
// Block of 256 threads handles 4 source nodes; 64 threads per node, each
// owns one float4 (4 cols). All 16 gathers issued before the FMA chain (MLP).
// NOTE: indices are int32 (JAX x64-disabled demotes int64 -> int32).
// ---------------------------------------------------------------------------
__global__ __launch_bounds__(256) void agg_kernel(
    const float4* __restrict__ sup,          // supports as float4 [N*64]
    const int* __restrict__ src_idx,         // [S] int32
    const int* __restrict__ neighs,          // [S, 16] int32
    const float* __restrict__ mask,          // [S, 16]
    int S)
{
    __shared__ int   nb[4][KNB];
    __shared__ float mk[4][KNB];
    __shared__ int   src[4];

    const int s_base = blockIdx.x * 4;
    const int tid = threadIdx.x;

    if (tid < 64) {
        int sl = tid >> 4, k = tid & 15;
        int s = s_base + sl;
        if (s < S) nb[sl][k] = neighs[(size_t)s * KNB + k];
    } else if (tid < 128) {
        int u = tid - 64;
        int sl = u >> 4, k = u & 15;
        int s = s_base + sl;
        if (s < S) mk[sl][k] = mask[(size_t)s * KNB + k];
    } else if (tid < 132) {
        int sl = tid - 128;
        int s = s_base + sl;
        if (s < S) src[sl] = src_idx[s];
    }
    __syncthreads();

    const int sl = tid >> 6;
    const int q  = tid & 63;
    const int s  = s_base + sl;
    if (s >= S) return;

    // Issue all gathers first: 17 independent float4 loads in flight.
    float4 v[KNB];
#pragma unroll
    for (int k = 0; k < KNB; k++)
        v[k] = sup[(size_t)nb[sl][k] * (D / 4) + q];
    float4 acc = sup[(size_t)src[sl] * (D / 4) + q];

#pragma unroll
    for (int k = 0; k < KNB; k++) {
        float m = mk[sl][k];
        acc.x = fmaf(m, v[k].x, acc.x);
        acc.y = fmaf(m, v[k].y, acc.y);
        acc.z = fmaf(m, v[k].z, acc.z);
        acc.w = fmaf(m, v[k].w, acc.w);
    }
    // LeakyReLU(0.2)
    acc.x = acc.x >= 0.f ? acc.x : 0.2f * acc.x;
    acc.y = acc.y >= 0.f ? acc.y : 0.2f * acc.y;
    acc.z = acc.z >= 0.f ? acc.z : 0.2f * acc.z;
    acc.w = acc.w >= 0.f ? acc.w : 0.2f * acc.w;

    g_scratch[(size_t)s * (D / 4) + q] = acc;
}

// ---------------------------------------------------------------------------
// Kernel 3: supports[src_idx[s]] += scratch[s]   (src_idx unique -> no atomics)
// ---------------------------------------------------------------------------
__global__ __launch_bounds__(256) void scatter_kernel(
    float4* __restrict__ sup,
    const int* __restrict__ src_idx,
    int S)
{
    long long i = (long long)blockIdx.x * 256 + threadIdx.x;  // over S*64 float4
    int s = (int)(i >> 6);
    int q = (int)(i & 63);
    if (s >= S) return;
    int r = src_idx[s];
    float4 a = sup[(size_t)r * (D / 4) + q];
    float4 bv = g_scratch[(size_t)s * (D / 4) + q];
    a.x += bv.x; a.y += bv.y; a.z += bv.z; a.w += bv.w;
    sup[(size_t)r * (D / 4) + q] = a;
}

// ---------------------------------------------------------------------------
extern "C" void kernel_launch(void* const* d_in, const int* in_sizes, int n_in,
                              void* d_out, int out_size)
{
    const float* wv     = (const float*)d_in[0];   // [N, 256]
    const int*   src    = (const int*)d_in[1];     // [S] int32
    const int*   neighs = (const int*)d_in[2];     // [S, 16] int32
    const float* mask   = (const float*)d_in[3];   // [S, 16]
    const float* W      = (const float*)d_in[4];   // [256, 256]
    const float* bias   = (const float*)d_in[5];   // [256]
    float*       out    = (float*)d_out;           // [N, 256]

    const int N = in_sizes[0] / D;
    const int S = in_sizes[1];

    // 1) supports = wv @ W^T + b  -> out
    dim3 gemm_grid((N + 127) / 128, D / 128);
    gemm_bias_kernel<<<gemm_grid, 256>>>(wv, W, bias, out, N);

    // 2) aggregation (reads pre-update supports) -> scratch
    int agg_blocks = (S + 3) / 4;
    agg_kernel<<<agg_blocks, 256>>>((const float4*)out, src, neighs, mask, S);

    // 3) scatter-add
    long long total4 = (long long)S * (D / 4);
    int sc_blocks = (int)((total4 + 255) / 256);
    scatter_kernel<<<sc_blocks, 256>>>((float4*)out, src, S);
}

// round 4
// speedup vs baseline: 2.2118x; 2.2118x over previous
#include <cuda_runtime.h>
#include <cuda_bf16.h>
#include <cstdint>

#define D         256
#define KNB       16
#define S_MAX     50000
#define N_MAX     100000

// Static scratch (no allocations allowed)
__device__ float4        g_scratch[(size_t)S_MAX * (D / 4)];
__device__ __nv_bfloat16 g_Ahi[(size_t)N_MAX * D];
__device__ __nv_bfloat16 g_Alo[(size_t)N_MAX * D];
__device__ __nv_bfloat16 g_Whi[D * D];
__device__ __nv_bfloat16 g_Wlo[D * D];

__device__ __forceinline__ uint32_t smem_u32(const void* p) {
    uint32_t a;
    asm("{ .reg .u64 t; cvta.to.shared.u64 t, %1; cvt.u32.u64 %0, t; }" : "=r"(a) : "l"(p));
    return a;
}
__device__ __forceinline__ void ldsm4(uint32_t& r0, uint32_t& r1, uint32_t& r2, uint32_t& r3,
                                      uint32_t addr) {
    asm volatile("ldmatrix.sync.aligned.m8n8.x4.shared.b16 {%0,%1,%2,%3}, [%4];"
                 : "=r"(r0), "=r"(r1), "=r"(r2), "=r"(r3) : "r"(addr));
}
__device__ __forceinline__ void mma16816(float* d, const uint32_t* a, uint32_t b0, uint32_t b1) {
    asm volatile(
        "mma.sync.aligned.m16n8k16.row.col.f32.bf16.bf16.f32 "
        "{%0,%1,%2,%3}, {%4,%5,%6,%7}, {%8,%9}, {%0,%1,%2,%3};"
        : "+f"(d[0]), "+f"(d[1]), "+f"(d[2]), "+f"(d[3])
        : "r"(a[0]), "r"(a[1]), "r"(a[2]), "r"(a[3]), "r"(b0), "r"(b1));
}

// ---------------------------------------------------------------------------
// Kernel 0: split fp32 -> bf16 hi + lo
// ---------------------------------------------------------------------------
__global__ __launch_bounds__(256) void split_kernel(
    const float4* __restrict__ src, uint2* __restrict__ hi, uint2* __restrict__ lo, int n4)
{
    int i = blockIdx.x * 256 + threadIdx.x;
    if (i >= n4) return;
    float4 v = src[i];
    __nv_bfloat16 hx = __float2bfloat16_rn(v.x), hy = __float2bfloat16_rn(v.y);
    __nv_bfloat16 hz = __float2bfloat16_rn(v.z), hw = __float2bfloat16_rn(v.w);
    __nv_bfloat16 lx = __float2bfloat16_rn(v.x - __bfloat162float(hx));
    __nv_bfloat16 ly = __float2bfloat16_rn(v.y - __bfloat162float(hy));
    __nv_bfloat16 lz = __float2bfloat16_rn(v.z - __bfloat162float(hz));
    __nv_bfloat16 lw = __float2bfloat16_rn(v.w - __bfloat162float(hw));
    __nv_bfloat162 h01 = __halves2bfloat162(hx, hy), h23 = __halves2bfloat162(hz, hw);
    __nv_bfloat162 l01 = __halves2bfloat162(lx, ly), l23 = __halves2bfloat162(lz, lw);
    uint2 ho, loo;
    ho.x  = *(uint32_t*)&h01; ho.y  = *(uint32_t*)&h23;
    loo.x = *(uint32_t*)&l01; loo.y = *(uint32_t*)&l23;
    hi[i] = ho; lo[i] = loo;
}

// ---------------------------------------------------------------------------
// Kernel 1: bf16-split GEMM via mma.sync (HMMA).  C[M,256] = A @ W^T + b
// CTA tile 128x128 (grid.y = 2 N-halves). 8 warps (2 x 4), warp tile 64x32.
// K chunk = 16. smem row stride 48B (conflict-free ldmatrix).
// ---------------------------------------------------------------------------
#define ROWH 24   // halfs per smem row (48 bytes)

__global__ __launch_bounds__(256) void gemm_mma_kernel(
    const float* __restrict__ bias, float* __restrict__ C, int M)
{
    __shared__ __align__(16) uint16_t sAh[128 * ROWH];
    __shared__ __align__(16) uint16_t sAl[128 * ROWH];
    __shared__ __align__(16) uint16_t sWh[128 * ROWH];
    __shared__ __align__(16) uint16_t sWl[128 * ROWH];

    const int tid  = threadIdx.x;
    const int lane = tid & 31;
    const int wid  = tid >> 5;
    const int wm   = wid & 1;          // 0..1 -> 64-row slab
    const int wn   = wid >> 1;         // 0..3 -> 32-col slab
    const int row0 = blockIdx.x * 128;
    const int col0 = blockIdx.y * 128;

    const uint32_t bAh = smem_u32(sAh), bAl = smem_u32(sAl);
    const uint32_t bWh = smem_u32(sWh), bWl = smem_u32(sWl);

    float acc[4][4][4];
#pragma unroll
    for (int i = 0; i < 4; i++)
#pragma unroll
        for (int j = 0; j < 4; j++)
#pragma unroll
            for (int q = 0; q < 4; q++) acc[i][j][q] = 0.f;

    // gmem load coords: thread t loads 8 halfs; r = t>>1, sel = t&1
    const int lr  = tid >> 1;
    const int sel = tid & 1;
    const int arow = row0 + lr;
    const size_t aoff = (size_t)arow * D + sel * 8;
    const size_t woff = (size_t)(col0 + lr) * D + sel * 8;
    const uint32_t sstore = (uint32_t)(lr * 48 + sel * 16);  // byte offset in tile

    // ldmatrix fragment address offsets (bytes)
    const uint32_t frag_off = (uint32_t)((lane & 15) * 48 + (lane >> 4) * 16);

    for (int c = 0; c < 16; c++) {
        // ---- load k-chunk c into smem ----
        uint4 vh = make_uint4(0, 0, 0, 0), vl = make_uint4(0, 0, 0, 0);
        if (arow < M) {
            vh = *(const uint4*)(g_Ahi + aoff + c * 16);
            vl = *(const uint4*)(g_Alo + aoff + c * 16);
        }
        uint4 wh = *(const uint4*)(g_Whi + woff + c * 16);
        uint4 wl = *(const uint4*)(g_Wlo + woff + c * 16);
        *(uint4*)((char*)sAh + sstore) = vh;
        *(uint4*)((char*)sAl + sstore) = vl;
        *(uint4*)((char*)sWh + sstore) = wh;
        *(uint4*)((char*)sWl + sstore) = wl;
        __syncthreads();

        // ---- fragments ----
        uint32_t ah[4][4], al[4][4];
#pragma unroll
        for (int mt = 0; mt < 4; mt++) {
            uint32_t off = (uint32_t)((wm * 64 + mt * 16) * 48) + frag_off;
            ldsm4(ah[mt][0], ah[mt][1], ah[mt][2], ah[mt][3], bAh + off);
            ldsm4(al[mt][0], al[mt][1], al[mt][2], al[mt][3], bAl + off);
        }
        uint32_t bh[2][2][2], bl[2][2][2];   // [npair][ntile][reg]
#pragma unroll
        for (int np = 0; np < 2; np++) {
            uint32_t off = (uint32_t)((wn * 32 + np * 16) * 48) + frag_off;
            uint32_t r0, r1, r2, r3;
            ldsm4(r0, r1, r2, r3, bWh + off);
            bh[np][0][0] = r0; bh[np][0][1] = r2;
            bh[np][1][0] = r1; bh[np][1][1] = r3;
            ldsm4(r0, r1, r2, r3, bWl + off);
            bl[np][0][0] = r0; bl[np][0][1] = r2;
            bl[np][1][0] = r1; bl[np][1][1] = r3;
        }

        // ---- mma: 4 mt x 4 nt x 3 passes ----
#pragma unroll
        for (int mt = 0; mt < 4; mt++) {
#pragma unroll
            for (int nt = 0; nt < 4; nt++) {
                int np = nt >> 1, ni = nt & 1;
                mma16816(acc[mt][nt], ah[mt], bh[np][ni][0], bh[np][ni][1]);
                mma16816(acc[mt][nt], al[mt], bh[np][ni][0], bh[np][ni][1]);
                mma16816(acc[mt][nt], ah[mt], bl[np][ni][0], bl[np][ni][1]);
            }
        }
        __syncthreads();
    }

    // ---- epilogue: bias + store ----
#pragma unroll
    for (int mt = 0; mt < 4; mt++) {
        int r0 = row0 + wm * 64 + mt * 16 + (lane >> 2);
        int r1 = r0 + 8;
#pragma unroll
        for (int nt = 0; nt < 4; nt++) {
            int cb = col0 + wn * 32 + nt * 8 + 2 * (lane & 3);
            float b0 = bias[cb], b1 = bias[cb + 1];
            if (r0 < M) {
                float2 o = make_float2(acc[mt][nt][0] + b0, acc[mt][nt][1] + b1);
                *(float2*)(C + (size_t)r0 * D + cb) = o;
            }
            if (r1 < M) {
                float2 o = make_float2(acc[mt][nt][2] + b0, acc[mt][nt][3] + b1);
                *(float2*)(C + (size_t)r1 * D + cb) = o;
            }
        }
    }
}

// ---------------------------------------------------------------------------
// Kernel 2: masked neighbor aggregation + residual + LeakyReLU -> scratch.
// ---------------------------------------------------------------------------
__global__ __launch_bounds__(256) void agg_kernel(
    const float4* __restrict__ sup,
    const int* __restrict__ src_idx,
    const int* __restrict__ neighs,
    const float* __restrict__ mask,
    int S)
{
    __shared__ int   nb[4][KNB];
    __shared__ float mk[4][KNB];
    __shared__ int   src[4];

    const int s_base = blockIdx.x * 4;
    const int tid = threadIdx.x;

    if (tid < 64) {
        int sl = tid >> 4, k = tid & 15;
        int s = s_base + sl;
        if (s < S) nb[sl][k] = neighs[(size_t)s * KNB + k];
    } else if (tid < 128) {
        int u = tid - 64;
        int sl = u >> 4, k = u & 15;
        int s = s_base + sl;
        if (s < S) mk[sl][k] = mask[(size_t)s * KNB + k];
    } else if (tid < 132) {
        int sl = tid - 128;
        int s = s_base + sl;
        if (s < S) src[sl] = src_idx[s];
    }
    __syncthreads();

    const int sl = tid >> 6;
    const int q  = tid & 63;
    const int s  = s_base + sl;
    if (s >= S) return;

    float4 v[KNB];
#pragma unroll
    for (int k = 0; k < KNB; k++)
        v[k] = sup[(size_t)nb[sl][k] * (D / 4) + q];
    float4 acc = sup[(size_t)src[sl] * (D / 4) + q];

#pragma unroll
    for (int k = 0; k < KNB; k++) {
        float m = mk[sl][k];
        acc.x = fmaf(m, v[k].x, acc.x);
        acc.y = fmaf(m, v[k].y, acc.y);
        acc.z = fmaf(m, v[k].z, acc.z);
        acc.w = fmaf(m, v[k].w, acc.w);
    }
    acc.x = acc.x >= 0.f ? acc.x : 0.2f * acc.x;
    acc.y = acc.y >= 0.f ? acc.y : 0.2f * acc.y;
    acc.z = acc.z >= 0.f ? acc.z : 0.2f * acc.z;
    acc.w = acc.w >= 0.f ? acc.w : 0.2f * acc.w;

    g_scratch[(size_t)s * (D / 4) + q] = acc;
}

// ---------------------------------------------------------------------------
// Kernel 3: supports[src_idx[s]] += scratch[s]
// ---------------------------------------------------------------------------
__global__ __launch_bounds__(256) void scatter_kernel(
    float4* __restrict__ sup, const int* __restrict__ src_idx, int S)
{
    long long i = (long long)blockIdx.x * 256 + threadIdx.x;
    int s = (int)(i >> 6);
    int q = (int)(i & 63);
    if (s >= S) return;
    int r = src_idx[s];
    float4 a = sup[(size_t)r * (D / 4) + q];
    float4 bv = g_scratch[(size_t)s * (D / 4) + q];
    a.x += bv.x; a.y += bv.y; a.z += bv.z; a.w += bv.w;
    sup[(size_t)r * (D / 4) + q] = a;
}

// ---------------------------------------------------------------------------
extern "C" void kernel_launch(void* const* d_in, const int* in_sizes, int n_in,
                              void* d_out, int out_size)
{
    const float* wv     = (const float*)d_in[0];
    const int*   src    = (const int*)d_in[1];
    const int*   neighs = (const int*)d_in[2];
    const float* mask   = (const float*)d_in[3];
    const float* W      = (const float*)d_in[4];
    const float* bias   = (const float*)d_in[5];
    float*       out    = (float*)d_out;

    const int N = in_sizes[0] / D;
    const int S = in_sizes[1];

    // 0) split inputs to bf16 hi/lo
    {
        __nv_bfloat16 *ahi, *alo, *whi, *wlo;
        cudaGetSymbolAddress((void**)&ahi, g_Ahi);
        cudaGetSymbolAddress((void**)&alo, g_Alo);
        cudaGetSymbolAddress((void**)&whi, g_Whi);
        cudaGetSymbolAddress((void**)&wlo, g_Wlo);
        int a4 = N * (D / 4);
        split_kernel<<<(a4 + 255) / 256, 256>>>((const float4*)wv, (uint2*)ahi, (uint2*)alo, a4);
        int w4 = D * (D / 4);
        split_kernel<<<(w4 + 255) / 256, 256>>>((const float4*)W, (uint2*)whi, (uint2*)wlo, w4);
    }

    // 1) tensor-core GEMM + bias -> out
    dim3 grid((N + 127) / 128, 2);
    gemm_mma_kernel<<<grid, 256>>>(bias, out, N);

    // 2) aggregation -> scratch
    agg_kernel<<<(S + 3) / 4, 256>>>((const float4*)out, src, neighs, mask, S);

    // 3) scatter-add
    long long total4 = (long long)S * (D / 4);
    scatter_kernel<<<(int)((total4 + 255) / 256), 256>>>((float4*)out, src, S);
}

// round 10
// speedup vs baseline: 2.6630x; 1.2040x over previous
#include <cuda_runtime.h>
#include <cuda_bf16.h>
#include <cstdint>

#define D         256
#define KNB       16
#define S_MAX     50000
#define N_MAX     100000

// Static scratch: snapshot of pre-update supports rows [0, S)
__device__ float4        g_snap[(size_t)S_MAX * (D / 4)];
__device__ __nv_bfloat16 g_Whi[D * D];
__device__ __nv_bfloat16 g_Wlo[D * D];

__device__ __forceinline__ uint32_t smem_u32(const void* p) {
    uint32_t a;
    asm("{ .reg .u64 t; cvta.to.shared.u64 t, %1; cvt.u32.u64 %0, t; }" : "=r"(a) : "l"(p));
    return a;
}
__device__ __forceinline__ void ldsm4(uint32_t& r0, uint32_t& r1, uint32_t& r2, uint32_t& r3,
                                      uint32_t addr) {
    asm volatile("ldmatrix.sync.aligned.m8n8.x4.shared.b16 {%0,%1,%2,%3}, [%4];"
                 : "=r"(r0), "=r"(r1), "=r"(r2), "=r"(r3) : "r"(addr));
}
__device__ __forceinline__ void mma16816(float* d, const uint32_t* a, uint32_t b0, uint32_t b1) {
    asm volatile(
        "mma.sync.aligned.m16n8k16.row.col.f32.bf16.bf16.f32 "
        "{%0,%1,%2,%3}, {%4,%5,%6,%7}, {%8,%9}, {%0,%1,%2,%3};"
        : "+f"(d[0]), "+f"(d[1]), "+f"(d[2]), "+f"(d[3])
        : "r"(a[0]), "r"(a[1]), "r"(a[2]), "r"(a[3]), "r"(b0), "r"(b1));
}
// pack 4 fp32 -> bf16 hi (uint2) and lo (uint2)
__device__ __forceinline__ void split4(const float* f, uint2& hi, uint2& lo) {
    uint32_t h[2], l[2];
#pragma unroll
    for (int i = 0; i < 2; i++) {
        __nv_bfloat16 h0 = __float2bfloat16_rn(f[2 * i + 0]);
        __nv_bfloat16 h1 = __float2bfloat16_rn(f[2 * i + 1]);
        __nv_bfloat16 l0 = __float2bfloat16_rn(f[2 * i + 0] - __bfloat162float(h0));
        __nv_bfloat16 l1 = __float2bfloat16_rn(f[2 * i + 1] - __bfloat162float(h1));
        __nv_bfloat162 hp = __halves2bfloat162(h0, h1);
        __nv_bfloat162 lp = __halves2bfloat162(l0, l1);
        h[i] = *(uint32_t*)&hp;
        l[i] = *(uint32_t*)&lp;
    }
    hi = make_uint2(h[0], h[1]);
    lo = make_uint2(l[0], l[1]);
}

// ---------------------------------------------------------------------------
// Kernel 0: split W (fp32 -> bf16 hi + lo). Tiny: 64K elements.
// ---------------------------------------------------------------------------
__global__ __launch_bounds__(256) void splitW_kernel(
    const float4* __restrict__ src, uint2* __restrict__ hi, uint2* __restrict__ lo, int n4)
{
    int i = blockIdx.x * 256 + threadIdx.x;
    if (i >= n4) return;
    float4 v = src[i];
    uint2 h, l;
    split4((const float*)&v, h, l);
    hi[i] = h; lo[i] = l;
}

// ---------------------------------------------------------------------------
// Kernel 1: bf16-split GEMM via mma.sync, fused fp32->bf16 A conversion,
// double-buffered smem, snapshot write for rows < S.
// CTA tile 128x256 (full N). 16 warps 2x8, warp tile 64x32. K chunk 16.
// A fp32 read exactly ONCE from gmem.
// ---------------------------------------------------------------------------
#define ROWB    48             // bytes per smem row (24 halfs, padded)
#define A_TILE  (128 * ROWB)   // 6144
#define W_TILE  (256 * ROWB)   // 12288
#define BUF_B   (2 * A_TILE + 2 * W_TILE)   // 36864
// buffer layout: [Ah(0), Al(6144), Wh(12288), Wl(24576)]
#define SMEM_GEMM_TOTAL (2 * BUF_B)         // 73728

__global__ __launch_bounds__(512) void gemm_mma_kernel(
    const float* __restrict__ A,   // fp32 [M, 256]
    const float* __restrict__ bias,
    float* __restrict__ C, int M, int S)
{
    extern __shared__ char dsm[];
    const int tid  = threadIdx.x;
    const int lane = tid & 31;
    const int wid  = tid >> 5;         // 0..15
    const int wm   = wid & 1;          // 2 slabs of 64 rows
    const int wn   = wid >> 1;         // 8 slabs of 32 cols
    const int row0 = blockIdx.x * 128;

    const uint32_t sb = smem_u32(dsm);

    float acc[4][4][4];
#pragma unroll
    for (int i = 0; i < 4; i++)
#pragma unroll
        for (int j = 0; j < 4; j++)
#pragma unroll
            for (int q = 0; q < 4; q++) acc[i][j][q] = 0.f;

    // A loads: 128 rows x 16 k fp32 per chunk = 2048 floats; 512 thr x 4 floats
    const int lr   = tid >> 2;         // 0..127
    const int sel  = tid & 3;          // k quarter (4 floats)
    const int arow = row0 + lr;
    const bool a_ok = arow < M;
    const float* aptr = A + (size_t)arow * D + sel * 4;
    const uint32_t astore = (uint32_t)(lr * ROWB + sel * 8);
    // W loads: 256 rows x 16 k bf16 per chunk = 4096 halfs; 512 thr x 8 halfs
    const int wr   = tid >> 1;         // 0..255
    const int wsel = tid & 1;          // k half (8 halfs)
    const __nv_bfloat16* whp = g_Whi + (size_t)wr * D + wsel * 8;
    const __nv_bfloat16* wlp = g_Wlo + (size_t)wr * D + wsel * 8;
    const uint32_t wstore = (uint32_t)(wr * ROWB + wsel * 16);

    const uint32_t frag_off = (uint32_t)((lane & 15) * ROWB + (lane >> 4) * 16);

    // staging registers
    float af[4];
    uint4 whv, wlv;

    // prologue: load chunk 0
    if (a_ok) *(float4*)af = *(const float4*)aptr;
    else { af[0] = af[1] = af[2] = af[3] = 0.f; }
    whv = *(const uint4*)whp;
    wlv = *(const uint4*)wlp;

    for (int c = 0; c < 16; c++) {
        const int cur = c & 1;
        char* base = dsm + cur * BUF_B;
        // convert + store current chunk
        uint2 ahv, alv;
        split4(af, ahv, alv);
        *(uint2*)(base + 0 * A_TILE + astore) = ahv;
        *(uint2*)(base + 1 * A_TILE + astore) = alv;
        *(uint4*)(base + 2 * A_TILE + wstore) = whv;
        *(uint4*)(base + 2 * A_TILE + W_TILE + wstore) = wlv;
        __syncthreads();

        // prefetch next chunk (overlaps with mma below)
        if (c < 15) {
            const int o = (c + 1) * 16;
            if (a_ok) *(float4*)af = *(const float4*)(aptr + o);
            whv = *(const uint4*)(whp + o);
            wlv = *(const uint4*)(wlp + o);
        }

        const uint32_t bb = sb + cur * BUF_B;
        uint32_t ah[4][4], al[4][4];
#pragma unroll
        for (int mt = 0; mt < 4; mt++) {
            uint32_t off = (uint32_t)((wm * 64 + mt * 16) * ROWB) + frag_off;
            ldsm4(ah[mt][0], ah[mt][1], ah[mt][2], ah[mt][3], bb + 0 * A_TILE + off);
            ldsm4(al[mt][0], al[mt][1], al[mt][2], al[mt][3], bb + 1 * A_TILE + off);
        }
        uint32_t bh[2][2][2], bl[2][2][2];
#pragma unroll
        for (int np = 0; np < 2; np++) {
            uint32_t off = (uint32_t)((wn * 32 + np * 16) * ROWB) + frag_off;
            uint32_t r0, r1, r2, r3;
            ldsm4(r0, r1, r2, r3, bb + 2 * A_TILE + off);
            bh[np][0][0] = r0; bh[np][0][1] = r2;
            bh[np][1][0] = r1; bh[np][1][1] = r3;
            ldsm4(r0, r1, r2, r3, bb + 2 * A_TILE + W_TILE + off);
            bl[np][0][0] = r0; bl[np][0][1] = r2;
            bl[np][1][0] = r1; bl[np][1][1] = r3;
        }

#pragma unroll
        for (int mt = 0; mt < 4; mt++) {
#pragma unroll
            for (int nt = 0; nt < 4; nt++) {
                int np = nt >> 1, ni = nt & 1;
                mma16816(acc[mt][nt], ah[mt], bh[np][ni][0], bh[np][ni][1]);
                mma16816(acc[mt][nt], al[mt], bh[np][ni][0], bh[np][ni][1]);
                mma16816(acc[mt][nt], ah[mt], bl[np][ni][0], bl[np][ni][1]);
            }
        }
        // no trailing sync: next iter writes the other buffer; its sync
        // guarantees all warps finished reading this one before reuse.
    }

    // epilogue: bias + store (and snapshot for rows < S)
    float* snap = (float*)g_snap;
#pragma unroll
    for (int mt = 0; mt < 4; mt++) {
        int r0 = row0 + wm * 64 + mt * 16 + (lane >> 2);
        int r1 = r0 + 8;
#pragma unroll
        for (int nt = 0; nt < 4; nt++) {
            int cb = wn * 32 + nt * 8 + 2 * (lane & 3);
            float b0 = bias[cb], b1 = bias[cb + 1];
            if (r0 < M) {
                float2 o = make_float2(acc[mt][nt][0] + b0, acc[mt][nt][1] + b1);
                *(float2*)(C + (size_t)r0 * D + cb) = o;
                if (r0 < S) *(float2*)(snap + (size_t)r0 * D + cb) = o;
            }
            if (r1 < M) {
                float2 o = make_float2(acc[mt][nt][2] + b0, acc[mt][nt][3] + b1);
                *(float2*)(C + (size_t)r1 * D + cb) = o;
                if (r1 < S) *(float2*)(snap + (size_t)r1 * D + cb) = o;
            }
        }
    }
}

// ---------------------------------------------------------------------------
// Kernel 2 (fused agg + scatter): for each source s (src_idx unique):
//   r = src_idx[s]
//   val = pre-update supports row r (snap if r < S else C)
//   o   = LeakyReLU(sum_k mask[s,k] * feat(nb) + val),  feat(nb) = nb<S ? snap : C
//   C[r] = val + o
// ---------------------------------------------------------------------------
__global__ __launch_bounds__(256) void agg_kernel(
    float4* __restrict__ sup,              // C, updated in place for scattered rows
    const int* __restrict__ src_idx,
    const int* __restrict__ neighs,
    const float* __restrict__ mask,
    int S)
{
    __shared__ int   nb[4][KNB];
    __shared__ float mk[4][KNB];
    __shared__ int   src[4];

    const int s_base = blockIdx.x * 4;
    const int tid = threadIdx.x;

    if (tid < 64) {
        int sl = tid >> 4, k = tid & 15;
        int s = s_base + sl;
        if (s < S) nb[sl][k] = neighs[(size_t)s * KNB + k];
    } else if (tid < 128) {
        int u = tid - 64;
        int sl = u >> 4, k = u & 15;
        int s = s_base + sl;
        if (s < S) mk[sl][k] = mask[(size_t)s * KNB + k];
    } else if (tid < 132) {
        int sl = tid - 128;
        int s = s_base + sl;
        if (s < S) src[sl] = src_idx[s];
    }
    __syncthreads();

    const int sl = tid >> 6;
    const int q  = tid & 63;
    const int s  = s_base + sl;
    if (s >= S) return;

    const float4* snap = (const float4*)g_snap;

    float4 v[KNB];
#pragma unroll
    for (int k = 0; k < KNB; k++) {
        int n = nb[sl][k];
        const float4* basep = (n < S) ? snap : sup;
        v[k] = basep[(size_t)n * (D / 4) + q];
    }
    const int r = src[sl];
    float4 val = (r < S) ? snap[(size_t)r * (D / 4) + q]
                         : sup[(size_t)r * (D / 4) + q];

    float4 acc = val;
#pragma unroll
    for (int k = 0; k < KNB; k++) {
        float m = mk[sl][k];
        acc.x = fmaf(m, v[k].x, acc.x);
        acc.y = fmaf(m, v[k].y, acc.y);
        acc.z = fmaf(m, v[k].z, acc.z);
        acc.w = fmaf(m, v[k].w, acc.w);
    }
    acc.x = acc.x >= 0.f ? acc.x : 0.2f * acc.x;
    acc.y = acc.y >= 0.f ? acc.y : 0.2f * acc.y;
    acc.z = acc.z >= 0.f ? acc.z : 0.2f * acc.z;
    acc.w = acc.w >= 0.f ? acc.w : 0.2f * acc.w;

    float4 o;
    o.x = val.x + acc.x; o.y = val.y + acc.y;
    o.z = val.z + acc.z; o.w = val.w + acc.w;
    sup[(size_t)r * (D / 4) + q] = o;
}

// ---------------------------------------------------------------------------
extern "C" void kernel_launch(void* const* d_in, const int* in_sizes, int n_in,
                              void* d_out, int out_size)
{
    const float* wv     = (const float*)d_in[0];
    const int*   src    = (const int*)d_in[1];
    const int*   neighs = (const int*)d_in[2];
    const float* mask   = (const float*)d_in[3];
    const float* W      = (const float*)d_in[4];
    const float* bias   = (const float*)d_in[5];
    float*       out    = (float*)d_out;

    const int N = in_sizes[0] / D;
    const int S = in_sizes[1];

    // 0) split W to bf16 hi/lo (tiny)
    {
        __nv_bfloat16 *whi, *wlo;
        cudaGetSymbolAddress((void**)&whi, g_Whi);
        cudaGetSymbolAddress((void**)&wlo, g_Wlo);
        int w4 = D * (D / 4);
        splitW_kernel<<<(w4 + 255) / 256, 256>>>((const float4*)W, (uint2*)whi, (uint2*)wlo, w4);
    }

    // 1) tensor-core GEMM + bias -> out (+ snapshot rows < S)
    cudaFuncSetAttribute(gemm_mma_kernel, cudaFuncAttributeMaxDynamicSharedMemorySize,
                         SMEM_GEMM_TOTAL);
    gemm_mma_kernel<<<(N + 127) / 128, 512, SMEM_GEMM_TOTAL>>>(wv, bias, out, N, S);

    // 2) fused aggregation + residual + LeakyReLU + in-place scatter-add
    agg_kernel<<<(S + 3) / 4, 256>>>((float4*)out, src, neighs, mask, S);
}